// round 11
// baseline (speedup 1.0000x reference)
#include <cuda_runtime.h>
#include <math.h>

#define CHUNKS   16
#define RES_DIM  8192
#define NB       18      // blocks per chunk: 288 blocks = one wave at 2 blocks/SM
#define THREADS  1024

// Tiny per-chunk arrival counters (zero-initialized at module load; the last
// block of each chunk resets its counter every launch -> replay-safe).
__device__ int g_done[CHUNKS];

// ---------------------------------------------------------------------------
// Kernel 0: zero d_out (write-only; d_out is the spmv atomic accumulator)
// ---------------------------------------------------------------------------
__global__ void zero_kernel(float4* __restrict__ out, int n4) {
    int i = blockIdx.x * blockDim.x + threadIdx.x;
    if (i < n4) out[i] = make_float4(0.f, 0.f, 0.f, 0.f);
}

// ---------------------------------------------------------------------------
// Kernel 1: per-chunk COO SpMV with smem accumulation (scalar unroll-4 loads)
// + fused Horner epilogue run by the last-arriving block of each chunk.
// ---------------------------------------------------------------------------
__global__ __launch_bounds__(THREADS)
void spmv_kernel(const float* __restrict__ vals,
                 const int*   __restrict__ rows,
                 const int*   __restrict__ cols,
                 const float* __restrict__ state,
                 const float* __restrict__ proj,
                 float*       __restrict__ out,
                 int nse,
                 float k0, float k1, float k2, float k3, float k4, float k5) {
    extern __shared__ float smem[];
    float* acc = smem;            // RES_DIM floats
    float* st  = smem + RES_DIM;  // RES_DIM floats

    const int c   = blockIdx.y;
    const int blk = blockIdx.x;

    const float* __restrict__ st_g = state + (size_t)c * RES_DIM;
    for (int j = threadIdx.x; j < RES_DIM; j += THREADS) {
        acc[j] = 0.0f;
        st[j]  = st_g[j];
    }
    __syncthreads();

    const size_t base = (size_t)c * (size_t)nse;
    const float* __restrict__ v  = vals + base;
    const int*   __restrict__ r  = rows + base;
    const int*   __restrict__ cl = cols + base;

    const int per = (nse + NB - 1) / NB;
    const int lo  = blk * per;
    const int hi  = min(lo + per, nse);

    int i = lo + threadIdx.x;
    // scalar unroll-4: 12 independent LDG.32 in flight before the smem work
    for (; i + 3 * THREADS < hi; i += 4 * THREADS) {
        float v0 = v[i];               int r0 = r[i];               int c0 = cl[i];
        float v1 = v[i +     THREADS]; int r1 = r[i +     THREADS]; int c1 = cl[i +     THREADS];
        float v2 = v[i + 2 * THREADS]; int r2 = r[i + 2 * THREADS]; int c2 = cl[i + 2 * THREADS];
        float v3 = v[i + 3 * THREADS]; int r3 = r[i + 3 * THREADS]; int c3 = cl[i + 3 * THREADS];
        atomicAdd(&acc[r0], v0 * st[c0]);
        atomicAdd(&acc[r1], v1 * st[c1]);
        atomicAdd(&acc[r2], v2 * st[c2]);
        atomicAdd(&acc[r3], v3 * st[c3]);
    }
    for (; i < hi; i += THREADS) {
        atomicAdd(&acc[r[i]], v[i] * st[cl[i]]);
    }
    __syncthreads();

    // Flush partials into out (zero-seeded by zero_kernel).
    float* __restrict__ o = out + (size_t)c * RES_DIM;
    for (int j = threadIdx.x; j < RES_DIM; j += THREADS) {
        atomicAdd(&o[j], acc[j]);
    }

    // Completion: last-arriving block of this chunk applies proj + Horner.
    __threadfence();
    __shared__ int s_last;
    if (threadIdx.x == 0) {
        int ticket = atomicAdd(&g_done[c], 1);
        s_last = (ticket == NB - 1) ? 1 : 0;
    }
    __syncthreads();

    if (s_last) {
        const float* __restrict__ pj = proj + (size_t)c * RES_DIM;
        for (int j = threadIdx.x; j < RES_DIM; j += THREADS) {
            float z = __ldcg(&o[j]) + pj[j];
            float p = k5;
            p = fmaf(z, p, k4);
            p = fmaf(z, p, k3);
            p = fmaf(z, p, k2);
            p = fmaf(z, p, k1);
            p = fmaf(z, p, k0);
            __stcg(&o[j], p);
        }
        if (threadIdx.x == 0) g_done[c] = 0;   // reset for next replay
    }
}

// ---------------------------------------------------------------------------
extern "C" void kernel_launch(void* const* d_in, const int* in_sizes, int n_in,
                              void* d_out, int out_size) {
    const float* proj  = (const float*)d_in[0];
    const float* state = (const float*)d_in[1];
    const float* vals  = (const float*)d_in[2];
    const int*   rows  = (const int*)  d_in[3];
    const int*   cols  = (const int*)  d_in[4];
    float*       out   = (float*)d_out;

    const int nse = in_sizes[2] / CHUNKS;
    const int n4  = out_size / 4;   // CHUNKS*RES_DIM/4

    // Taylor coefficients of tanh(1.6 + z) around z=0, fp32 (matches reference)
    const float t  = tanhf(1.6f);
    const float t2 = t * t, t3 = t2 * t, t4 = t2 * t2, t6 = t4 * t2;
    const float k0 = t;
    const float k1 = 1.0f - t2;
    const float k2 = t3 - t;
    const float k3 = -t4 + (4.0f / 3.0f) * t2 - 1.0f / 3.0f;
    const float k4 = (t / 3.0f) * (3.0f * t4 - 5.0f * t2 + 2.0f);
    const float k5 = -t6 + 2.0f * t4 - (17.0f / 15.0f) * t2 + 2.0f / 15.0f;

    const int smem_bytes = 2 * RES_DIM * sizeof(float);  // 64KB
    cudaFuncSetAttribute(spmv_kernel, cudaFuncAttributeMaxDynamicSharedMemorySize, smem_bytes);

    zero_kernel<<<(n4 + 511) / 512, 512>>>((float4*)out, n4);

    dim3 grid(NB, CHUNKS);
    spmv_kernel<<<grid, THREADS, smem_bytes>>>(vals, rows, cols, state, proj, out,
                                               nse, k0, k1, k2, k3, k4, k5);
}